// round 8
// baseline (speedup 1.0000x reference)
#include <cuda_runtime.h>

#define H 64
#define B 16
#define L 512
#define TOK_PER_BLOCK 8
#define TOKENS_PER_BATCH (2 * L)                              // 1024
#define CHUNKS_PER_BATCH (TOKENS_PER_BATCH / TOK_PER_BLOCK)   // 128
#define NBLOCKS (B * CHUNKS_PER_BATCH)                        // 2048

// Zero-initialized accumulator. mlp_kernel resets it after use, so every
// graph replay starts from zeros (deterministic).
__device__ float g_h[B * H];

// ---------------------------------------------------------------------------
// accum_kernel: one block = one batch b, 8 tokens, 256 threads.
// Thread layout: c4 = t & 15  -> float4 column (h = c4*4 .. c4*4+3)
//                wg = t >> 4  -> row group; rows w = wg + 16*it, it=0..3
// Token indices preloaded to smem; 2 tokens in flight -> 8 front-batched
// LDG.128 per thread. Block partial goes straight into g_h via REDG
// (no-return atomicAdd, spread over 1024 addresses) — no partial buffer,
// no threadfence, no L1 flush.
// ---------------------------------------------------------------------------
__global__ void __launch_bounds__(256, 4) accum_kernel(
    const int* __restrict__ s1, const int* __restrict__ s2,
    const float* __restrict__ embed, const float* __restrict__ sos_g)
{
    __shared__ float s_sos[H];
    __shared__ float s_red[H];
    __shared__ int   s_tok[TOK_PER_BLOCK];

    const int t     = threadIdx.x;
    const int blk   = blockIdx.x;
    const int b     = blk / CHUNKS_PER_BATCH;
    const int chunk = blk % CHUNKS_PER_BATCH;
    const int tok0  = chunk * TOK_PER_BLOCK;       // in [0, 1024)

    if (t < H) { s_sos[t] = sos_g[t]; s_red[t] = 0.0f; }
    if (t < TOK_PER_BLOCK) {
        const int ti = tok0 + t;
        s_tok[t] = (ti < L) ? s1[b * L + ti] : s2[b * L + (ti - L)];
    }
    __syncthreads();

    const int c4 = t & 15;    // float4 column index
    const int wg = t >> 4;    // row group 0..15

    float acc0 = 0.f, acc1 = 0.f, acc2 = 0.f, acc3 = 0.f;

    #pragma unroll
    for (int k = 0; k < TOK_PER_BLOCK; k += 2) {
        const float4* E0 = (const float4*)(embed) + (size_t)s_tok[k]     * (H * H / 4);
        const float4* E1 = (const float4*)(embed) + (size_t)s_tok[k + 1] * (H * H / 4);

        float4 v0[4], v1[4];
        #pragma unroll
        for (int it = 0; it < 4; ++it)
            v0[it] = __ldg(&E0[(wg + 16 * it) * 16 + c4]);
        #pragma unroll
        for (int it = 0; it < 4; ++it)
            v1[it] = __ldg(&E1[(wg + 16 * it) * 16 + c4]);

        #pragma unroll
        for (int it = 0; it < 4; ++it) {
            const float sw = s_sos[wg + 16 * it];
            acc0 = fmaf(sw, v0[it].x, acc0);
            acc1 = fmaf(sw, v0[it].y, acc1);
            acc2 = fmaf(sw, v0[it].z, acc2);
            acc3 = fmaf(sw, v0[it].w, acc3);
        }
        #pragma unroll
        for (int it = 0; it < 4; ++it) {
            const float sw = s_sos[wg + 16 * it];
            acc0 = fmaf(sw, v1[it].x, acc0);
            acc1 = fmaf(sw, v1[it].y, acc1);
            acc2 = fmaf(sw, v1[it].z, acc2);
            acc3 = fmaf(sw, v1[it].w, acc3);
        }
    }

    // Fold lanes l and l+16 (same c4, adjacent row-groups) inside each warp.
    acc0 += __shfl_xor_sync(0xffffffffu, acc0, 16);
    acc1 += __shfl_xor_sync(0xffffffffu, acc1, 16);
    acc2 += __shfl_xor_sync(0xffffffffu, acc2, 16);
    acc3 += __shfl_xor_sync(0xffffffffu, acc3, 16);

    // 8 remaining row-group partials per h -> shared atomics (spread addrs).
    if ((t & 31) < 16) {
        const int hb = c4 * 4;
        atomicAdd(&s_red[hb + 0], acc0);
        atomicAdd(&s_red[hb + 1], acc1);
        atomicAdd(&s_red[hb + 2], acc2);
        atomicAdd(&s_red[hb + 3], acc3);
    }
    __syncthreads();

    // Fire-and-forget global accumulation (REDG), 64 spread addresses/block.
    if (t < H) atomicAdd(&g_h[b * H + t], s_red[t]);
}

// ---------------------------------------------------------------------------
// mlp_kernel: ONE block, 512 threads = 16 warps; warp b handles batch b.
// Reads the 1024-float accumulator, computes Linear+ReLU+Linear, writes out,
// then resets g_h for the next graph replay.
// ---------------------------------------------------------------------------
__global__ void __launch_bounds__(512) mlp_kernel(
    const float* __restrict__ w1, const float* __restrict__ b1,
    const float* __restrict__ w2, const float* __restrict__ b2,
    float* __restrict__ out)
{
    __shared__ float s_hv[B * H];
    const int t = threadIdx.x;

    #pragma unroll
    for (int i = t; i < B * H; i += 512)
        s_hv[i] = g_h[i];
    __syncthreads();

    // Reset accumulator for next replay (after all threads have copied).
    #pragma unroll
    for (int i = t; i < B * H; i += 512)
        g_h[i] = 0.0f;

    const int warp = t >> 5;   // batch index
    const int lane = t & 31;
    const float* hv = s_hv + warp * H;

    float x0 = b1[lane];
    float x1 = b1[lane + 32];
    #pragma unroll
    for (int k = 0; k < H; ++k) {
        const float hk = hv[k];
        x0 = fmaf(hk, w1[lane * H + k],        x0);
        x1 = fmaf(hk, w1[(lane + 32) * H + k], x1);
    }
    x0 = fmaxf(x0, 0.0f);
    x1 = fmaxf(x1, 0.0f);

    float o0 = x0 * w2[lane]     + x1 * w2[lane + 32];
    float o1 = x0 * w2[H + lane] + x1 * w2[H + lane + 32];
    #pragma unroll
    for (int off = 16; off > 0; off >>= 1) {
        o0 += __shfl_xor_sync(0xffffffffu, o0, off);
        o1 += __shfl_xor_sync(0xffffffffu, o1, off);
    }
    if (lane == 0) {
        out[warp * 2 + 0] = o0 + b2[0];
        out[warp * 2 + 1] = o1 + b2[1];
    }
}

extern "C" void kernel_launch(void* const* d_in, const int* in_sizes, int n_in,
                              void* d_out, int out_size) {
    const int*   s1    = (const int*)  d_in[0];
    const int*   s2    = (const int*)  d_in[1];
    const float* embed = (const float*)d_in[2];
    const float* sos   = (const float*)d_in[3];
    const float* w1    = (const float*)d_in[4];
    const float* b1    = (const float*)d_in[5];
    const float* w2    = (const float*)d_in[6];
    const float* b2    = (const float*)d_in[7];
    float* out = (float*)d_out;

    accum_kernel<<<NBLOCKS, 256>>>(s1, s2, embed, sos);
    mlp_kernel<<<1, 512>>>(w1, b1, w2, b2, out);
}

// round 9
// speedup vs baseline: 1.7538x; 1.7538x over previous
#include <cuda_runtime.h>

#define H 64
#define B 16
#define L 512
#define TOK_PER_BLOCK 8
#define TOKENS_PER_BATCH (2 * L)                              // 1024
#define CHUNKS_PER_BATCH (TOKENS_PER_BATCH / TOK_PER_BLOCK)   // 128
#define NBLOCKS (B * CHUNKS_PER_BATCH)                        // 2048

#define W1PAD 68   // padded row length for conflict-free LDS.128 streams

// Zero-initialized accumulator. mlp_kernel resets it after use, so every
// graph replay starts from zeros (deterministic).
__device__ float g_h[B * H];

// ---------------------------------------------------------------------------
// accum_kernel: one block = one batch b, 8 tokens, 256 threads. (unchanged —
// measured ~36.5us, ~7TB/s effective, near roofline)
// ---------------------------------------------------------------------------
__global__ void __launch_bounds__(256, 4) accum_kernel(
    const int* __restrict__ s1, const int* __restrict__ s2,
    const float* __restrict__ embed, const float* __restrict__ sos_g)
{
    __shared__ float s_sos[H];
    __shared__ float s_red[H];
    __shared__ int   s_tok[TOK_PER_BLOCK];

    const int t     = threadIdx.x;
    const int blk   = blockIdx.x;
    const int b     = blk / CHUNKS_PER_BATCH;
    const int chunk = blk % CHUNKS_PER_BATCH;
    const int tok0  = chunk * TOK_PER_BLOCK;       // in [0, 1024)

    if (t < H) { s_sos[t] = sos_g[t]; s_red[t] = 0.0f; }
    if (t < TOK_PER_BLOCK) {
        const int ti = tok0 + t;
        s_tok[t] = (ti < L) ? s1[b * L + ti] : s2[b * L + (ti - L)];
    }
    __syncthreads();

    const int c4 = t & 15;    // float4 column index
    const int wg = t >> 4;    // row group 0..15

    float acc0 = 0.f, acc1 = 0.f, acc2 = 0.f, acc3 = 0.f;

    #pragma unroll
    for (int k = 0; k < TOK_PER_BLOCK; k += 2) {
        const float4* E0 = (const float4*)(embed) + (size_t)s_tok[k]     * (H * H / 4);
        const float4* E1 = (const float4*)(embed) + (size_t)s_tok[k + 1] * (H * H / 4);

        float4 v0[4], v1[4];
        #pragma unroll
        for (int it = 0; it < 4; ++it)
            v0[it] = __ldg(&E0[(wg + 16 * it) * 16 + c4]);
        #pragma unroll
        for (int it = 0; it < 4; ++it)
            v1[it] = __ldg(&E1[(wg + 16 * it) * 16 + c4]);

        #pragma unroll
        for (int it = 0; it < 4; ++it) {
            const float sw = s_sos[wg + 16 * it];
            acc0 = fmaf(sw, v0[it].x, acc0);
            acc1 = fmaf(sw, v0[it].y, acc1);
            acc2 = fmaf(sw, v0[it].z, acc2);
            acc3 = fmaf(sw, v0[it].w, acc3);
        }
        #pragma unroll
        for (int it = 0; it < 4; ++it) {
            const float sw = s_sos[wg + 16 * it];
            acc0 = fmaf(sw, v1[it].x, acc0);
            acc1 = fmaf(sw, v1[it].y, acc1);
            acc2 = fmaf(sw, v1[it].z, acc2);
            acc3 = fmaf(sw, v1[it].w, acc3);
        }
    }

    acc0 += __shfl_xor_sync(0xffffffffu, acc0, 16);
    acc1 += __shfl_xor_sync(0xffffffffu, acc1, 16);
    acc2 += __shfl_xor_sync(0xffffffffu, acc2, 16);
    acc3 += __shfl_xor_sync(0xffffffffu, acc3, 16);

    if ((t & 31) < 16) {
        const int hb = c4 * 4;
        atomicAdd(&s_red[hb + 0], acc0);
        atomicAdd(&s_red[hb + 1], acc1);
        atomicAdd(&s_red[hb + 2], acc2);
        atomicAdd(&s_red[hb + 3], acc3);
    }
    __syncthreads();

    // Fire-and-forget global accumulation (REDG), 64 spread addresses/block.
    if (t < H) atomicAdd(&g_h[b * H + t], s_red[t]);
}

// ---------------------------------------------------------------------------
// mlp_kernel: ONE block, 512 threads.
// Phase 1: coalesced float4 staging of w1/w2/b1/b2/g_h into shared memory
//          (w1 rows padded to 68 floats -> conflict-free LDS.128 in phase 2).
// Phase 2: warp b computes batch b entirely from smem.
// Also resets g_h for the next graph replay.
// ---------------------------------------------------------------------------
__global__ void __launch_bounds__(512) mlp_kernel(
    const float* __restrict__ w1, const float* __restrict__ b1,
    const float* __restrict__ w2, const float* __restrict__ b2,
    float* __restrict__ out)
{
    __shared__ float s_w1[H * W1PAD];   // padded [64][68]
    __shared__ float s_h[B * H];        // 1024
    __shared__ float s_w2[2 * H];       // 128
    __shared__ float s_b1[H];           // 64
    __shared__ float s_b2[2];

    const int t = threadIdx.x;

    // ---- coalesced staging ----
    // w1: 4096 floats = 1024 float4; 512 threads x 2 iterations.
    {
        const float4* w1v = (const float4*)w1;
        #pragma unroll
        for (int i4 = t; i4 < (H * H) / 4; i4 += 512) {
            const float4 v = __ldg(&w1v[i4]);
            const int j  = i4 >> 4;          // row
            const int k4 = (i4 & 15) * 4;    // col base
            // j*W1PAD + k4 is a multiple of 4 -> 16B-aligned STS.128
            *(float4*)(&s_w1[j * W1PAD + k4]) = v;
        }
    }
    // g_h: 1024 floats; copy to smem then reset for next replay.
    #pragma unroll
    for (int i = t; i < B * H; i += 512) s_h[i] = g_h[i];
    if (t < 2 * H) s_w2[t] = __ldg(&w2[t]);
    if (t >= 2 * H && t < 3 * H) s_b1[t - 2 * H] = __ldg(&b1[t - 2 * H]);
    if (t == 500) { s_b2[0] = __ldg(&b2[0]); s_b2[1] = __ldg(&b2[1]); }
    __syncthreads();

    #pragma unroll
    for (int i = t; i < B * H; i += 512) g_h[i] = 0.0f;

    // ---- compute: warp b handles batch b ----
    const int warp = t >> 5;
    const int lane = t & 31;
    const float* hv   = s_h + warp * H;
    const float* row0 = s_w1 + lane * W1PAD;
    const float* row1 = s_w1 + (lane + 32) * W1PAD;

    float x0 = s_b1[lane];
    float x1 = s_b1[lane + 32];
    #pragma unroll
    for (int k = 0; k < H; k += 4) {
        const float4 hk = *(const float4*)(hv + k);
        const float4 a  = *(const float4*)(row0 + k);
        const float4 c  = *(const float4*)(row1 + k);
        x0 = fmaf(hk.x, a.x, x0); x0 = fmaf(hk.y, a.y, x0);
        x0 = fmaf(hk.z, a.z, x0); x0 = fmaf(hk.w, a.w, x0);
        x1 = fmaf(hk.x, c.x, x1); x1 = fmaf(hk.y, c.y, x1);
        x1 = fmaf(hk.z, c.z, x1); x1 = fmaf(hk.w, c.w, x1);
    }
    x0 = fmaxf(x0, 0.0f);
    x1 = fmaxf(x1, 0.0f);

    float o0 = x0 * s_w2[lane]     + x1 * s_w2[lane + 32];
    float o1 = x0 * s_w2[H + lane] + x1 * s_w2[H + lane + 32];
    #pragma unroll
    for (int off = 16; off > 0; off >>= 1) {
        o0 += __shfl_xor_sync(0xffffffffu, o0, off);
        o1 += __shfl_xor_sync(0xffffffffu, o1, off);
    }
    if (lane == 0) {
        out[warp * 2 + 0] = o0 + s_b2[0];
        out[warp * 2 + 1] = o1 + s_b2[1];
    }
}

extern "C" void kernel_launch(void* const* d_in, const int* in_sizes, int n_in,
                              void* d_out, int out_size) {
    const int*   s1    = (const int*)  d_in[0];
    const int*   s2    = (const int*)  d_in[1];
    const float* embed = (const float*)d_in[2];
    const float* sos   = (const float*)d_in[3];
    const float* w1    = (const float*)d_in[4];
    const float* b1    = (const float*)d_in[5];
    const float* w2    = (const float*)d_in[6];
    const float* b2    = (const float*)d_in[7];
    float* out = (float*)d_out;

    accum_kernel<<<NBLOCKS, 256>>>(s1, s2, embed, sos);
    mlp_kernel<<<1, 512>>>(w1, b1, w2, b2, out);
}

// round 10
// speedup vs baseline: 1.7552x; 1.0008x over previous
#include <cuda_runtime.h>

#define H 64
#define B 16
#define L 512
#define TOK_PER_BLOCK 8
#define TOKENS_PER_BATCH (2 * L)                              // 1024
#define CHUNKS_PER_BATCH (TOKENS_PER_BATCH / TOK_PER_BLOCK)   // 128
#define NBLOCKS (B * CHUNKS_PER_BATCH)                        // 2048

#define W1PAD 68   // padded row length for conflict-free LDS.128 streams

// Zero-initialized accumulator. mlp_kernel resets it after use, so every
// graph replay starts from zeros (deterministic).
__device__ float g_h[B * H];

// ---------------------------------------------------------------------------
// accum_kernel: one block = one batch b, 8 tokens, 256 threads.
// (measured ~36us, ~7TB/s effective — near roofline; unchanged except for the
// early PDL trigger so mlp_kernel can pre-stage its weights concurrently)
// ---------------------------------------------------------------------------
__global__ void __launch_bounds__(256, 4) accum_kernel(
    const int* __restrict__ s1, const int* __restrict__ s2,
    const float* __restrict__ embed, const float* __restrict__ sos_g)
{
    __shared__ float s_sos[H];
    __shared__ float s_red[H];
    __shared__ int   s_tok[TOK_PER_BLOCK];

    const int t     = threadIdx.x;
    const int blk   = blockIdx.x;
    const int b     = blk / CHUNKS_PER_BATCH;
    const int chunk = blk % CHUNKS_PER_BATCH;
    const int tok0  = chunk * TOK_PER_BLOCK;       // in [0, 1024)

    // Allow the dependent mlp_kernel to launch early (it only reads g_h after
    // cudaGridDependencySynchronize, which waits for this grid's completion).
    cudaTriggerProgrammaticLaunchCompletion();

    if (t < H) { s_sos[t] = sos_g[t]; s_red[t] = 0.0f; }
    if (t < TOK_PER_BLOCK) {
        const int ti = tok0 + t;
        s_tok[t] = (ti < L) ? s1[b * L + ti] : s2[b * L + (ti - L)];
    }
    __syncthreads();

    const int c4 = t & 15;    // float4 column index
    const int wg = t >> 4;    // row group 0..15

    float acc0 = 0.f, acc1 = 0.f, acc2 = 0.f, acc3 = 0.f;

    #pragma unroll
    for (int k = 0; k < TOK_PER_BLOCK; k += 2) {
        const float4* E0 = (const float4*)(embed) + (size_t)s_tok[k]     * (H * H / 4);
        const float4* E1 = (const float4*)(embed) + (size_t)s_tok[k + 1] * (H * H / 4);

        float4 v0[4], v1[4];
        #pragma unroll
        for (int it = 0; it < 4; ++it)
            v0[it] = __ldg(&E0[(wg + 16 * it) * 16 + c4]);
        #pragma unroll
        for (int it = 0; it < 4; ++it)
            v1[it] = __ldg(&E1[(wg + 16 * it) * 16 + c4]);

        #pragma unroll
        for (int it = 0; it < 4; ++it) {
            const float sw = s_sos[wg + 16 * it];
            acc0 = fmaf(sw, v0[it].x, acc0);
            acc1 = fmaf(sw, v0[it].y, acc1);
            acc2 = fmaf(sw, v0[it].z, acc2);
            acc3 = fmaf(sw, v0[it].w, acc3);
        }
        #pragma unroll
        for (int it = 0; it < 4; ++it) {
            const float sw = s_sos[wg + 16 * it];
            acc0 = fmaf(sw, v1[it].x, acc0);
            acc1 = fmaf(sw, v1[it].y, acc1);
            acc2 = fmaf(sw, v1[it].z, acc2);
            acc3 = fmaf(sw, v1[it].w, acc3);
        }
    }

    acc0 += __shfl_xor_sync(0xffffffffu, acc0, 16);
    acc1 += __shfl_xor_sync(0xffffffffu, acc1, 16);
    acc2 += __shfl_xor_sync(0xffffffffu, acc2, 16);
    acc3 += __shfl_xor_sync(0xffffffffu, acc3, 16);

    if ((t & 31) < 16) {
        const int hb = c4 * 4;
        atomicAdd(&s_red[hb + 0], acc0);
        atomicAdd(&s_red[hb + 1], acc1);
        atomicAdd(&s_red[hb + 2], acc2);
        atomicAdd(&s_red[hb + 3], acc3);
    }
    __syncthreads();

    // Fire-and-forget global accumulation (REDG), 64 spread addresses/block.
    if (t < H) atomicAdd(&g_h[b * H + t], s_red[t]);
}

// ---------------------------------------------------------------------------
// mlp_kernel: ONE block, 512 threads, launched with PDL.
// Phase 0 (overlapped with accum): coalesced float4 staging of w1/w2/b1/b2
//          into shared memory (w1 rows padded to 68 floats).
// cudaGridDependencySynchronize() -> accum grid complete, g_h visible.
// Phase 1: copy g_h to smem, reset it for next replay.
// Phase 2: warp b computes batch b entirely from smem.
// ---------------------------------------------------------------------------
__global__ void __launch_bounds__(512) mlp_kernel(
    const float* __restrict__ w1, const float* __restrict__ b1,
    const float* __restrict__ w2, const float* __restrict__ b2,
    float* __restrict__ out)
{
    __shared__ float s_w1[H * W1PAD];   // padded [64][68]
    __shared__ float s_h[B * H];        // 1024
    __shared__ float s_w2[2 * H];       // 128
    __shared__ float s_b1[H];           // 64
    __shared__ float s_b2[2];

    const int t = threadIdx.x;

    // ---- phase 0: weight staging (overlaps with accum via PDL) ----
    {
        const float4* w1v = (const float4*)w1;
        #pragma unroll
        for (int i4 = t; i4 < (H * H) / 4; i4 += 512) {
            const float4 v = __ldg(&w1v[i4]);
            const int j  = i4 >> 4;          // row
            const int k4 = (i4 & 15) * 4;    // col base
            *(float4*)(&s_w1[j * W1PAD + k4]) = v;
        }
    }
    if (t < 2 * H) s_w2[t] = __ldg(&w2[t]);
    if (t >= 2 * H && t < 3 * H) s_b1[t - 2 * H] = __ldg(&b1[t - 2 * H]);
    if (t == 500) { s_b2[0] = __ldg(&b2[0]); s_b2[1] = __ldg(&b2[1]); }

    // ---- wait for accum grid; all its g_h REDGs become visible ----
    cudaGridDependencySynchronize();

    #pragma unroll
    for (int i = t; i < B * H; i += 512) s_h[i] = g_h[i];
    __syncthreads();

    // Reset accumulator for next graph replay.
    #pragma unroll
    for (int i = t; i < B * H; i += 512) g_h[i] = 0.0f;

    // ---- phase 2: warp b handles batch b ----
    const int warp = t >> 5;
    const int lane = t & 31;
    const float* hv   = s_h + warp * H;
    const float* row0 = s_w1 + lane * W1PAD;
    const float* row1 = s_w1 + (lane + 32) * W1PAD;

    float x0 = s_b1[lane];
    float x1 = s_b1[lane + 32];
    #pragma unroll
    for (int k = 0; k < H; k += 4) {
        const float4 hk = *(const float4*)(hv + k);
        const float4 a  = *(const float4*)(row0 + k);
        const float4 c  = *(const float4*)(row1 + k);
        x0 = fmaf(hk.x, a.x, x0); x0 = fmaf(hk.y, a.y, x0);
        x0 = fmaf(hk.z, a.z, x0); x0 = fmaf(hk.w, a.w, x0);
        x1 = fmaf(hk.x, c.x, x1); x1 = fmaf(hk.y, c.y, x1);
        x1 = fmaf(hk.z, c.z, x1); x1 = fmaf(hk.w, c.w, x1);
    }
    x0 = fmaxf(x0, 0.0f);
    x1 = fmaxf(x1, 0.0f);

    float o0 = x0 * s_w2[lane]     + x1 * s_w2[lane + 32];
    float o1 = x0 * s_w2[H + lane] + x1 * s_w2[H + lane + 32];
    #pragma unroll
    for (int off = 16; off > 0; off >>= 1) {
        o0 += __shfl_xor_sync(0xffffffffu, o0, off);
        o1 += __shfl_xor_sync(0xffffffffu, o1, off);
    }
    if (lane == 0) {
        out[warp * 2 + 0] = o0 + s_b2[0];
        out[warp * 2 + 1] = o1 + s_b2[1];
    }
}

extern "C" void kernel_launch(void* const* d_in, const int* in_sizes, int n_in,
                              void* d_out, int out_size) {
    const int*   s1    = (const int*)  d_in[0];
    const int*   s2    = (const int*)  d_in[1];
    const float* embed = (const float*)d_in[2];
    const float* sos   = (const float*)d_in[3];
    const float* w1    = (const float*)d_in[4];
    const float* b1    = (const float*)d_in[5];
    const float* w2    = (const float*)d_in[6];
    const float* b2    = (const float*)d_in[7];
    float* out = (float*)d_out;

    accum_kernel<<<NBLOCKS, 256>>>(s1, s2, embed, sos);

    // Launch mlp_kernel with Programmatic Dependent Launch so its weight
    // staging overlaps the accum kernel's tail.
    cudaLaunchConfig_t cfg = {};
    cfg.gridDim  = dim3(1, 1, 1);
    cfg.blockDim = dim3(512, 1, 1);
    cfg.dynamicSmemBytes = 0;
    cfg.stream = 0;  // same (legacy default) stream as the <<<>>> launch above

    cudaLaunchAttribute attrs[1];
    attrs[0].id = cudaLaunchAttributeProgrammaticStreamSerialization;
    attrs[0].val.programmaticStreamSerializationAllowed = 1;
    cfg.attrs = attrs;
    cfg.numAttrs = 1;

    cudaLaunchKernelEx(&cfg, mlp_kernel, w1, b1, w2, b2, out);
}